// round 14
// baseline (speedup 1.0000x reference)
#include <cuda_runtime.h>
#include <math_constants.h>

#define N_NODES 100000
#define N_EDGES 3200000
#define E_TOT   (N_EDGES + N_NODES)   // edges + self loops
#define F_IN    128
#define HID     32
#define NCLS    40
#define NEG_SLOPE 0.2f
#define NBLKS   392                   // grid for fused hist+scan (co-resident)
#define NBUCKET 8
#define NQUAD (N_EDGES / 4)           // 800000 quads of edges

// ---------------- scratch (device globals; zero-initialized) ----------------
__device__ float g_h1[N_NODES * HID];     // x @ W1
__device__ float g_s1[N_NODES];           // h1 . a_src1
__device__ float g_d1[N_NODES];           // h1 . a_dst1
__device__ float g_x2[N_NODES * HID];     // relu(agg1 + b1)
__device__ float g_s2[N_NODES];           // x2 . (W2 a_src2)
__device__ float g_d2[N_NODES];           // x2 . (W2 a_dst2)
__device__ float g_w2s[HID];
__device__ float g_w2d[HID];
__device__ int   g_deg[NBUCKET][N_NODES];     // bucketed degree counters (self-reset)
__device__ int   g_cursor[NBUCKET][N_NODES];  // bucketed scatter cursors
__device__ int   g_rowptr[N_NODES + 1];
__device__ int   g_csr_idx[E_TOT];            // src*HID
__device__ int   g_bsum[NBLKS];
__device__ int   g_ready;                     // grid-sync arrive counter (self-reset)

// ---------------- fused hist + scan (grid-resident, 392 blocks) ----------------
__device__ __forceinline__ void grid_sync(int threshold) {
    __syncthreads();
    if (threadIdx.x == 0) {
        __threadfence();
        atomicAdd(&g_ready, 1);
        while (((volatile int*)&g_ready)[0] < threshold) { }
    }
    __syncthreads();
}

__global__ __launch_bounds__(256) void k_histscan(const int* __restrict__ dst) {
    int t = threadIdx.x;
    int gtid = blockIdx.x * 256 + t;
    int gsz = NBLKS * 256;

    // ---- phase 1: bucketed histogram (fire-and-forget REDs) ----
    for (int i = gtid; i < NQUAD; i += gsz) {
        int4 d = reinterpret_cast<const int4*>(dst)[i];
        int* deg = g_deg[i & (NBUCKET - 1)];
        atomicAdd(&deg[d.x], 1);
        atomicAdd(&deg[d.y], 1);
        atomicAdd(&deg[d.z], 1);
        atomicAdd(&deg[d.w], 1);
    }
    grid_sync(NBLKS);

    // ---- phase 2: scan (1 node per thread) ----
    __shared__ int sh[256];
    __shared__ int blk_off;
    int node = gtid;   // 392*256 = 100352 >= N_NODES
    int dsum[NBUCKET];
    int d = 0;
    if (node < N_NODES) {
        d = 1;  // self loop
#pragma unroll
        for (int b = 0; b < NBUCKET; b++) {
            dsum[b] = g_deg[b][node];
            d += dsum[b];
        }
    }
    sh[t] = d;
    __syncthreads();
    for (int off = 1; off < 256; off <<= 1) {
        int u = (t >= off) ? sh[t - off] : 0;
        __syncthreads();
        sh[t] += u;
        __syncthreads();
    }
    int thr_excl = sh[t] - d;
    if (t == 0) g_bsum[blockIdx.x] = sh[255];
    grid_sync(2 * NBLKS);
    if (t == 0) {
        int off = 0;
#pragma unroll 8
        for (int b = 0; b < (int)blockIdx.x; b++) off += g_bsum[b];
        blk_off = off;
    }
    __syncthreads();

    if (node < N_NODES) {
        int run = blk_off + thr_excl;
        g_rowptr[node] = run;
        g_csr_idx[run] = node * HID;   // self loop at head (pre-scaled)
        int c = run + 1;
#pragma unroll
        for (int b = 0; b < NBUCKET; b++) {
            g_cursor[b][node] = c;
            c += dsum[b];
        }
    }
    if (node == N_NODES - 1) g_rowptr[N_NODES] = E_TOT;
}

// ---------------- scatter (big grid, idx only) + state reset ----------------
__global__ void k_scatter(const int* __restrict__ src, const int* __restrict__ dst) {
    int gtid = blockIdx.x * blockDim.x + threadIdx.x;
    int gsz = gridDim.x * blockDim.x;

    for (int i = gtid; i < NQUAD; i += gsz) {
        int4 s4 = reinterpret_cast<const int4*>(src)[i];
        int4 d4 = reinterpret_cast<const int4*>(dst)[i];
        int* cur = g_cursor[i & (NBUCKET - 1)];
        int p0 = atomicAdd(&cur[d4.x], 1);
        int p1 = atomicAdd(&cur[d4.y], 1);
        int p2 = atomicAdd(&cur[d4.z], 1);
        int p3 = atomicAdd(&cur[d4.w], 1);
        g_csr_idx[p0] = s4.x * HID;
        g_csr_idx[p1] = s4.y * HID;
        g_csr_idx[p2] = s4.z * HID;
        g_csr_idx[p3] = s4.w * HID;
    }

    // reset state for next graph replay
    for (int i = gtid; i < N_NODES; i += gsz) {
#pragma unroll
        for (int b = 0; b < NBUCKET; b++) g_deg[b][i] = 0;
    }
    if (gtid == 0) g_ready = 0;
}

// ---------------- GEMM1 (+fused prep): h1 = x @ W1, s1/d1; block 0 computes w2s/w2d ----
__global__ __launch_bounds__(256) void k_gemm1(const float* __restrict__ x,
                                               const float* __restrict__ W1,
                                               const float* __restrict__ a_src,
                                               const float* __restrict__ a_dst,
                                               const float* __restrict__ W2,
                                               const float* __restrict__ a_src2,
                                               const float* __restrict__ a_dst2) {
    __shared__ float Ws[F_IN * HID];
    __shared__ float asv[HID], adv[HID];
    for (int i = threadIdx.x; i < F_IN * HID; i += blockDim.x) Ws[i] = W1[i];
    if (threadIdx.x < HID) { asv[threadIdx.x] = a_src[threadIdx.x]; adv[threadIdx.x] = a_dst[threadIdx.x]; }

    if (blockIdx.x == 0 && threadIdx.x >= 224) {
        int k = threadIdx.x - 224;   // 0..31
        float s = 0.f, d = 0.f;
        const float* row = W2 + k * NCLS;
#pragma unroll
        for (int c = 0; c < NCLS; c++) {
            s = fmaf(row[c], a_src2[c], s);
            d = fmaf(row[c], a_dst2[c], d);
        }
        g_w2s[k] = s;
        g_w2d[k] = d;
    }
    __syncthreads();

    int n = blockIdx.x * blockDim.x + threadIdx.x;
    if (n >= N_NODES) return;

    float acc[HID];
#pragma unroll
    for (int c = 0; c < HID; c++) acc[c] = 0.f;

    const float4* xr = reinterpret_cast<const float4*>(x + (size_t)n * F_IN);
    const float4* Ws4 = reinterpret_cast<const float4*>(Ws);
#pragma unroll 4
    for (int k4 = 0; k4 < F_IN / 4; k4++) {
        float4 xv = xr[k4];
        int r = (k4 * 4) * (HID / 4);
#pragma unroll
        for (int c4 = 0; c4 < HID / 4; c4++) {
            float4 w0 = Ws4[r + c4];
            float4 w1 = Ws4[r + (HID / 4) + c4];
            float4 w2 = Ws4[r + 2 * (HID / 4) + c4];
            float4 w3 = Ws4[r + 3 * (HID / 4) + c4];
            int c = c4 * 4;
            acc[c+0] = fmaf(xv.x, w0.x, fmaf(xv.y, w1.x, fmaf(xv.z, w2.x, fmaf(xv.w, w3.x, acc[c+0]))));
            acc[c+1] = fmaf(xv.x, w0.y, fmaf(xv.y, w1.y, fmaf(xv.z, w2.y, fmaf(xv.w, w3.y, acc[c+1]))));
            acc[c+2] = fmaf(xv.x, w0.z, fmaf(xv.y, w1.z, fmaf(xv.z, w2.z, fmaf(xv.w, w3.z, acc[c+2]))));
            acc[c+3] = fmaf(xv.x, w0.w, fmaf(xv.y, w1.w, fmaf(xv.z, w2.w, fmaf(xv.w, w3.w, acc[c+3]))));
        }
    }
    float sv = 0.f, dv = 0.f;
#pragma unroll
    for (int c = 0; c < HID; c++) {
        g_h1[(size_t)n * HID + c] = acc[c];
        sv = fmaf(acc[c], asv[c], sv);
        dv = fmaf(acc[c], adv[c], dv);
    }
    g_s1[n] = sv;
    g_d1[n] = dv;
}

// ---- layer-1 aggregate: warp/dst, prefetch, hybrid branch-free inner loop ----
__global__ __launch_bounds__(256) void k_agg1(const float* __restrict__ b1) {
    __shared__ float2 shp[8][2][32];
    int tid = threadIdx.x;
    int wib = tid >> 5;
    int lane = tid & 31;
    int e = lane >> 3;        // edge slot 0..3
    int q = lane & 7;         // row quarter 0..7
    int n = (blockIdx.x * blockDim.x + tid) >> 5;
    if (n >= N_NODES) return;
    int beg = g_rowptr[n], end = g_rowptr[n + 1];
    float dn = g_d1[n];
    const float* hbase = g_h1 + q * 4;

    float denl = 0.f;
    float4 acc = make_float4(0.f, 0.f, 0.f, 0.f);
    int buf = 0;

    int base = beg;
    int idxH = g_csr_idx[base + min(lane, end - base - 1)];
    float sv  = g_s1[idxH >> 5];

    while (base < end) {
        int c = min(32, end - base);
        int nbase = base + 32;
        int nidxH = 0; float nsv = 0.f;
        if (nbase < end) {   // prefetch next chunk scalars
            nidxH = g_csr_idx[nbase + min(lane, end - nbase - 1)];
            nsv   = g_s1[nidxH >> 5];
        }

        float ev = sv + dn;
        ev = ev > 0.f ? ev : NEG_SLOPE * ev;
        float p = (lane < c) ? __expf(ev) : 0.f;
        denl += p;

        shp[wib][buf][lane] = make_float2(p, __int_as_float(idxH));
        __syncwarp();
        const float2* pr = &shp[wib][buf][e];
        if (c == 32) {
#pragma unroll
            for (int g = 0; g < 8; g++) {
                float2 qd = pr[g * 4];
                float4 hv = *reinterpret_cast<const float4*>(hbase + __float_as_int(qd.y));
                acc.x = fmaf(qd.x, hv.x, acc.x);
                acc.y = fmaf(qd.x, hv.y, acc.y);
                acc.z = fmaf(qd.x, hv.z, acc.z);
                acc.w = fmaf(qd.x, hv.w, acc.w);
            }
        } else {
            int ng = (c + 3) >> 2;
            for (int g = 0; g < ng; g++) {
                float2 qd = pr[g * 4];
                float4 hv = *reinterpret_cast<const float4*>(hbase + __float_as_int(qd.y));
                acc.x = fmaf(qd.x, hv.x, acc.x);
                acc.y = fmaf(qd.x, hv.y, acc.y);
                acc.z = fmaf(qd.x, hv.z, acc.z);
                acc.w = fmaf(qd.x, hv.w, acc.w);
            }
        }
        base = nbase; idxH = nidxH; sv = nsv; buf ^= 1;
    }

    float den = denl;
#pragma unroll
    for (int o = 16; o > 0; o >>= 1) den += __shfl_xor_sync(0xffffffffu, den, o);

#pragma unroll
    for (int o = 8; o <= 16; o <<= 1) {
        acc.x += __shfl_xor_sync(0xffffffffu, acc.x, o);
        acc.y += __shfl_xor_sync(0xffffffffu, acc.y, o);
        acc.z += __shfl_xor_sync(0xffffffffu, acc.z, o);
        acc.w += __shfl_xor_sync(0xffffffffu, acc.w, o);
    }

    float inv = 1.f / den;
    float4 b4 = reinterpret_cast<const float4*>(b1)[q];
    float4 v4;
    v4.x = fmaxf(fmaf(acc.x, inv, b4.x), 0.f);
    v4.y = fmaxf(fmaf(acc.y, inv, b4.y), 0.f);
    v4.z = fmaxf(fmaf(acc.z, inv, b4.z), 0.f);
    v4.w = fmaxf(fmaf(acc.w, inv, b4.w), 0.f);

    if (e == 0)
        reinterpret_cast<float4*>(g_x2 + (size_t)n * HID)[q] = v4;

    // s2/d2 projections (gemm2 fused away)
    float4 ws = reinterpret_cast<const float4*>(g_w2s)[q];
    float4 wd = reinterpret_cast<const float4*>(g_w2d)[q];
    float sp = v4.x * ws.x + v4.y * ws.y + v4.z * ws.z + v4.w * ws.w;
    float dp = v4.x * wd.x + v4.y * wd.y + v4.z * wd.z + v4.w * wd.w;
    if (e != 0) { sp = 0.f; dp = 0.f; }
#pragma unroll
    for (int o = 16; o > 0; o >>= 1) {
        sp += __shfl_xor_sync(0xffffffffu, sp, o);
        dp += __shfl_xor_sync(0xffffffffu, dp, o);
    }
    if (lane == 0) { g_s2[n] = sp; g_d2[n] = dp; }
}

// ---- layer-2: same loop shape as agg1; W2 epilogue + bias + relu + log_softmax ----
__global__ __launch_bounds__(256) void k_agg2(const float* __restrict__ W2,
                                              const float* __restrict__ b2,
                                              float* __restrict__ out) {
    __shared__ float W2s[HID * NCLS];
    __shared__ float2 shp[8][2][32];
    __shared__ float4 sx[8][8];
    for (int i = threadIdx.x; i < HID * NCLS; i += blockDim.x) W2s[i] = W2[i];
    __syncthreads();

    int tid = threadIdx.x;
    int wib = tid >> 5;
    int lane = tid & 31;
    int e = lane >> 3;
    int q = lane & 7;
    int n = (blockIdx.x * blockDim.x + tid) >> 5;
    if (n >= N_NODES) return;
    bool has2 = lane < (NCLS - 32);
    int beg = g_rowptr[n], end = g_rowptr[n + 1];
    float dn = g_d2[n];
    float b2l = b2[lane];
    float b2h = has2 ? b2[lane + 32] : 0.f;
    const float* hbase = g_x2 + q * 4;

    float denl = 0.f;
    float4 acc = make_float4(0.f, 0.f, 0.f, 0.f);
    int buf = 0;

    int base = beg;
    int idxH = g_csr_idx[base + min(lane, end - base - 1)];
    float sv  = g_s2[idxH >> 5];

    while (base < end) {
        int c = min(32, end - base);
        int nbase = base + 32;
        int nidxH = 0; float nsv = 0.f;
        if (nbase < end) {
            nidxH = g_csr_idx[nbase + min(lane, end - nbase - 1)];
            nsv   = g_s2[nidxH >> 5];
        }

        float ev = sv + dn;
        ev = ev > 0.f ? ev : NEG_SLOPE * ev;
        float p = (lane < c) ? __expf(ev) : 0.f;
        denl += p;

        shp[wib][buf][lane] = make_float2(p, __int_as_float(idxH));
        __syncwarp();
        const float2* pr = &shp[wib][buf][e];
        if (c == 32) {
#pragma unroll
            for (int g = 0; g < 8; g++) {
                float2 qd = pr[g * 4];
                float4 hv = *reinterpret_cast<const float4*>(hbase + __float_as_int(qd.y));
                acc.x = fmaf(qd.x, hv.x, acc.x);
                acc.y = fmaf(qd.x, hv.y, acc.y);
                acc.z = fmaf(qd.x, hv.z, acc.z);
                acc.w = fmaf(qd.x, hv.w, acc.w);
            }
        } else {
            int ng = (c + 3) >> 2;
            for (int g = 0; g < ng; g++) {
                float2 qd = pr[g * 4];
                float4 hv = *reinterpret_cast<const float4*>(hbase + __float_as_int(qd.y));
                acc.x = fmaf(qd.x, hv.x, acc.x);
                acc.y = fmaf(qd.x, hv.y, acc.y);
                acc.z = fmaf(qd.x, hv.z, acc.z);
                acc.w = fmaf(qd.x, hv.w, acc.w);
            }
        }
        base = nbase; idxH = nidxH; sv = nsv; buf ^= 1;
    }

    float den = denl;
#pragma unroll
    for (int o = 16; o > 0; o >>= 1) den += __shfl_xor_sync(0xffffffffu, den, o);

#pragma unroll
    for (int o = 8; o <= 16; o <<= 1) {
        acc.x += __shfl_xor_sync(0xffffffffu, acc.x, o);
        acc.y += __shfl_xor_sync(0xffffffffu, acc.y, o);
        acc.z += __shfl_xor_sync(0xffffffffu, acc.z, o);
        acc.w += __shfl_xor_sync(0xffffffffu, acc.w, o);
    }
    float inv = 1.f / den;
    acc.x *= inv; acc.y *= inv; acc.z *= inv; acc.w *= inv;

    if (e == 0) sx[wib][q] = acc;
    __syncwarp();

    // epilogue GEMM: h_out[c] = sum_k aggx_k * W2[k][c] + b2[c]
    float o0 = b2l;
    float o1 = b2h;
#pragma unroll
    for (int k4 = 0; k4 < 8; k4++) {
        float4 xv = sx[wib][k4];
        int k = k4 * 4;
        o0 = fmaf(xv.x, W2s[(k+0) * NCLS + lane], o0);
        o0 = fmaf(xv.y, W2s[(k+1) * NCLS + lane], o0);
        o0 = fmaf(xv.z, W2s[(k+2) * NCLS + lane], o0);
        o0 = fmaf(xv.w, W2s[(k+3) * NCLS + lane], o0);
        if (has2) {
            o1 = fmaf(xv.x, W2s[(k+0) * NCLS + lane + 32], o1);
            o1 = fmaf(xv.y, W2s[(k+1) * NCLS + lane + 32], o1);
            o1 = fmaf(xv.z, W2s[(k+2) * NCLS + lane + 32], o1);
            o1 = fmaf(xv.w, W2s[(k+3) * NCLS + lane + 32], o1);
        }
    }
    float v0 = fmaxf(o0, 0.f);
    float v1 = has2 ? fmaxf(o1, 0.f) : -CUDART_INF_F;

    float m = fmaxf(v0, v1);
#pragma unroll
    for (int o = 16; o > 0; o >>= 1) m = fmaxf(m, __shfl_xor_sync(0xffffffffu, m, o));
    float se = __expf(v0 - m) + (has2 ? __expf(v1 - m) : 0.f);
#pragma unroll
    for (int o = 16; o > 0; o >>= 1) se += __shfl_xor_sync(0xffffffffu, se, o);
    float lse = m + logf(se);

    out[(size_t)n * NCLS + lane] = v0 - lse;
    if (has2) out[(size_t)n * NCLS + lane + 32] = v1 - lse;
}

// ---------------- launch ----------------
extern "C" void kernel_launch(void* const* d_in, const int* in_sizes, int n_in,
                              void* d_out, int out_size) {
    const float* x        = (const float*)d_in[0];
    const int*   edge     = (const int*)  d_in[1];
    const float* W1       = (const float*)d_in[2];
    const float* att_src1 = (const float*)d_in[3];
    const float* att_dst1 = (const float*)d_in[4];
    const float* b1       = (const float*)d_in[5];
    const float* W2       = (const float*)d_in[6];
    const float* att_src2 = (const float*)d_in[7];
    const float* att_dst2 = (const float*)d_in[8];
    const float* b2       = (const float*)d_in[9];
    float* out = (float*)d_out;

    const int* src = edge;
    const int* dst = edge + N_EDGES;

    static cudaStream_t s2 = nullptr;
    static cudaEvent_t evFork = nullptr, evJoin = nullptr;
    if (!s2) {
        cudaStreamCreateWithFlags(&s2, cudaStreamNonBlocking);
        cudaEventCreateWithFlags(&evFork, cudaEventDisableTiming);
        cudaEventCreateWithFlags(&evJoin, cudaEventDisableTiming);
    }

    // fork: gemm1 (+fused prep) runs concurrent with the CSR build
    cudaEventRecord(evFork, 0);
    cudaStreamWaitEvent(s2, evFork, 0);
    k_gemm1<<<(N_NODES + 255) / 256, 256, 0, s2>>>(x, W1, att_src1, att_dst1,
                                                   W2, att_src2, att_dst2);
    cudaEventRecord(evJoin, s2);

    // main stream: CSR build (fused hist+scan grid-resident; scatter big-grid)
    k_histscan<<<NBLKS, 256>>>(dst);
    k_scatter<<<3125, 256>>>(src, dst);

    // join, then aggregates
    cudaStreamWaitEvent(0, evJoin, 0);
    k_agg1<<<(N_NODES * 32 + 255) / 256, 256>>>(b1);
    k_agg2<<<(N_NODES * 32 + 255) / 256, 256>>>(W2, b2, out);
}

// round 15
// speedup vs baseline: 1.0583x; 1.0583x over previous
#include <cuda_runtime.h>
#include <math_constants.h>

#define N_NODES 100000
#define N_EDGES 3200000
#define E_TOT   (N_EDGES + N_NODES)   // edges + self loops
#define F_IN    128
#define HID     32
#define NCLS    40
#define NEG_SLOPE 0.2f
#define NBLK    98                    // grid for scan kernel
#define NBUCKET 8
#define NQUAD (N_EDGES / 4)           // 800000 quads of edges

// ---------------- scratch (device globals; zero-initialized) ----------------
__device__ float g_h1[N_NODES * HID];     // x @ W1
__device__ float g_s1[N_NODES];           // h1 . a_src1
__device__ float g_d1[N_NODES];           // h1 . a_dst1
__device__ float g_x2[N_NODES * HID];     // relu(agg1 + b1)
__device__ float g_s2[N_NODES];           // x2 . (W2 a_src2)
__device__ float g_d2[N_NODES];           // x2 . (W2 a_dst2)
__device__ float g_w2s[HID];
__device__ float g_w2d[HID];
__device__ int   g_deg[NBUCKET][N_NODES];     // bucketed degree counters (self-reset)
__device__ int   g_cursor[NBUCKET][N_NODES];  // bucketed scatter cursors
__device__ int   g_rowptr[N_NODES + 1];
__device__ int   g_csr_idx[E_TOT];            // src*HID
__device__ int   g_bsum[NBLK];
__device__ int   g_ready;                     // scan arrive counter (self-reset)

// ---------------- hist: standalone big grid (1 quad/thread) ----------------
__global__ void k_hist(const int* __restrict__ dst) {
    int i = blockIdx.x * blockDim.x + threadIdx.x;
    if (i >= NQUAD) return;
    int4 d = reinterpret_cast<const int4*>(dst)[i];
    int* deg = g_deg[i & (NBUCKET - 1)];
    atomicAdd(&deg[d.x], 1);
    atomicAdd(&deg[d.y], 1);
    atomicAdd(&deg[d.z], 1);
    atomicAdd(&deg[d.w], 1);
}

// ---------------- scan: grid-resident 98 blocks, one internal grid sync ----------------
__device__ __forceinline__ void grid_sync(int threshold) {
    __syncthreads();
    if (threadIdx.x == 0) {
        __threadfence();
        atomicAdd(&g_ready, 1);
        while (((volatile int*)&g_ready)[0] < threshold) { }
    }
    __syncthreads();
}

__global__ __launch_bounds__(256) void k_scan() {
    __shared__ int sh[256];
    __shared__ int blk_off;
    int t = threadIdx.x;
    int base = blockIdx.x * 1024 + t * 4;
    int v[4];
    int dsum[4][NBUCKET];
    int s = 0;
#pragma unroll
    for (int k = 0; k < 4; k++) {
        int i = base + k;
        int d = 0;
        if (i < N_NODES) {
            d = 1;
#pragma unroll
            for (int b = 0; b < NBUCKET; b++) {
                dsum[k][b] = g_deg[b][i];
                d += dsum[k][b];
            }
        }
        v[k] = d;
        s += d;
    }
    sh[t] = s;
    __syncthreads();
    for (int off = 1; off < 256; off <<= 1) {
        int u = (t >= off) ? sh[t - off] : 0;
        __syncthreads();
        sh[t] += u;
        __syncthreads();
    }
    int thr_excl = sh[t] - s;
    if (t == 0) g_bsum[blockIdx.x] = sh[255];
    grid_sync(NBLK);
    if (t == 0) {
        int off = 0;
        for (int b = 0; b < (int)blockIdx.x; b++) off += g_bsum[b];
        blk_off = off;
    }
    __syncthreads();

    int run = blk_off + thr_excl;
#pragma unroll
    for (int k = 0; k < 4; k++) {
        int i = base + k;
        if (i < N_NODES) {
            g_rowptr[i] = run;
            g_csr_idx[run] = i * HID;        // self loop at head (pre-scaled)
            int c = run + 1;
#pragma unroll
            for (int b = 0; b < NBUCKET; b++) {
                g_cursor[b][i] = c;
                c += dsum[k][b];
            }
        }
        run += v[k];
    }
    if (blockIdx.x == NBLK - 1 && t == 255) g_rowptr[N_NODES] = E_TOT;
}

// ---------------- scatter (big grid, idx only) + state reset ----------------
__global__ void k_scatter(const int* __restrict__ src, const int* __restrict__ dst) {
    int gtid = blockIdx.x * blockDim.x + threadIdx.x;
    int gsz = gridDim.x * blockDim.x;

    for (int i = gtid; i < NQUAD; i += gsz) {
        int4 s4 = reinterpret_cast<const int4*>(src)[i];
        int4 d4 = reinterpret_cast<const int4*>(dst)[i];
        int* cur = g_cursor[i & (NBUCKET - 1)];
        int p0 = atomicAdd(&cur[d4.x], 1);
        int p1 = atomicAdd(&cur[d4.y], 1);
        int p2 = atomicAdd(&cur[d4.z], 1);
        int p3 = atomicAdd(&cur[d4.w], 1);
        g_csr_idx[p0] = s4.x * HID;
        g_csr_idx[p1] = s4.y * HID;
        g_csr_idx[p2] = s4.z * HID;
        g_csr_idx[p3] = s4.w * HID;
    }

    // reset state for next graph replay
    for (int i = gtid; i < N_NODES; i += gsz) {
#pragma unroll
        for (int b = 0; b < NBUCKET; b++) g_deg[b][i] = 0;
    }
    if (gtid == 0) g_ready = 0;
}

// ---------------- GEMM1 (+fused prep): h1 = x @ W1, s1/d1; block 0 computes w2s/w2d ----
__global__ __launch_bounds__(256) void k_gemm1(const float* __restrict__ x,
                                               const float* __restrict__ W1,
                                               const float* __restrict__ a_src,
                                               const float* __restrict__ a_dst,
                                               const float* __restrict__ W2,
                                               const float* __restrict__ a_src2,
                                               const float* __restrict__ a_dst2) {
    __shared__ float Ws[F_IN * HID];
    __shared__ float asv[HID], adv[HID];
    for (int i = threadIdx.x; i < F_IN * HID; i += blockDim.x) Ws[i] = W1[i];
    if (threadIdx.x < HID) { asv[threadIdx.x] = a_src[threadIdx.x]; adv[threadIdx.x] = a_dst[threadIdx.x]; }

    if (blockIdx.x == 0 && threadIdx.x >= 224) {
        int k = threadIdx.x - 224;   // 0..31
        float s = 0.f, d = 0.f;
        const float* row = W2 + k * NCLS;
#pragma unroll
        for (int c = 0; c < NCLS; c++) {
            s = fmaf(row[c], a_src2[c], s);
            d = fmaf(row[c], a_dst2[c], d);
        }
        g_w2s[k] = s;
        g_w2d[k] = d;
    }
    __syncthreads();

    int n = blockIdx.x * blockDim.x + threadIdx.x;
    if (n >= N_NODES) return;

    float acc[HID];
#pragma unroll
    for (int c = 0; c < HID; c++) acc[c] = 0.f;

    const float4* xr = reinterpret_cast<const float4*>(x + (size_t)n * F_IN);
    const float4* Ws4 = reinterpret_cast<const float4*>(Ws);
#pragma unroll 4
    for (int k4 = 0; k4 < F_IN / 4; k4++) {
        float4 xv = xr[k4];
        int r = (k4 * 4) * (HID / 4);
#pragma unroll
        for (int c4 = 0; c4 < HID / 4; c4++) {
            float4 w0 = Ws4[r + c4];
            float4 w1 = Ws4[r + (HID / 4) + c4];
            float4 w2 = Ws4[r + 2 * (HID / 4) + c4];
            float4 w3 = Ws4[r + 3 * (HID / 4) + c4];
            int c = c4 * 4;
            acc[c+0] = fmaf(xv.x, w0.x, fmaf(xv.y, w1.x, fmaf(xv.z, w2.x, fmaf(xv.w, w3.x, acc[c+0]))));
            acc[c+1] = fmaf(xv.x, w0.y, fmaf(xv.y, w1.y, fmaf(xv.z, w2.y, fmaf(xv.w, w3.y, acc[c+1]))));
            acc[c+2] = fmaf(xv.x, w0.z, fmaf(xv.y, w1.z, fmaf(xv.z, w2.z, fmaf(xv.w, w3.z, acc[c+2]))));
            acc[c+3] = fmaf(xv.x, w0.w, fmaf(xv.y, w1.w, fmaf(xv.z, w2.w, fmaf(xv.w, w3.w, acc[c+3]))));
        }
    }
    float sv = 0.f, dv = 0.f;
#pragma unroll
    for (int c = 0; c < HID; c++) {
        g_h1[(size_t)n * HID + c] = acc[c];
        sv = fmaf(acc[c], asv[c], sv);
        dv = fmaf(acc[c], adv[c], dv);
    }
    g_s1[n] = sv;
    g_d1[n] = dv;
}

// ---- layer-1 aggregate: warp/dst, prefetch, hybrid branch-free inner loop ----
__global__ __launch_bounds__(256) void k_agg1(const float* __restrict__ b1) {
    __shared__ float2 shp[8][2][32];
    int tid = threadIdx.x;
    int wib = tid >> 5;
    int lane = tid & 31;
    int e = lane >> 3;        // edge slot 0..3
    int q = lane & 7;         // row quarter 0..7
    int n = (blockIdx.x * blockDim.x + tid) >> 5;
    if (n >= N_NODES) return;
    int beg = g_rowptr[n], end = g_rowptr[n + 1];
    float dn = g_d1[n];
    const float* hbase = g_h1 + q * 4;

    float denl = 0.f;
    float4 acc = make_float4(0.f, 0.f, 0.f, 0.f);
    int buf = 0;

    int base = beg;
    int idxH = g_csr_idx[base + min(lane, end - base - 1)];
    float sv  = g_s1[idxH >> 5];

    while (base < end) {
        int c = min(32, end - base);
        int nbase = base + 32;
        int nidxH = 0; float nsv = 0.f;
        if (nbase < end) {   // prefetch next chunk scalars
            nidxH = g_csr_idx[nbase + min(lane, end - nbase - 1)];
            nsv   = g_s1[nidxH >> 5];
        }

        float ev = sv + dn;
        ev = ev > 0.f ? ev : NEG_SLOPE * ev;
        float p = (lane < c) ? __expf(ev) : 0.f;
        denl += p;

        shp[wib][buf][lane] = make_float2(p, __int_as_float(idxH));
        __syncwarp();
        const float2* pr = &shp[wib][buf][e];
        if (c == 32) {
#pragma unroll
            for (int g = 0; g < 8; g++) {
                float2 qd = pr[g * 4];
                float4 hv = *reinterpret_cast<const float4*>(hbase + __float_as_int(qd.y));
                acc.x = fmaf(qd.x, hv.x, acc.x);
                acc.y = fmaf(qd.x, hv.y, acc.y);
                acc.z = fmaf(qd.x, hv.z, acc.z);
                acc.w = fmaf(qd.x, hv.w, acc.w);
            }
        } else {
            int ng = (c + 3) >> 2;
            for (int g = 0; g < ng; g++) {
                float2 qd = pr[g * 4];
                float4 hv = *reinterpret_cast<const float4*>(hbase + __float_as_int(qd.y));
                acc.x = fmaf(qd.x, hv.x, acc.x);
                acc.y = fmaf(qd.x, hv.y, acc.y);
                acc.z = fmaf(qd.x, hv.z, acc.z);
                acc.w = fmaf(qd.x, hv.w, acc.w);
            }
        }
        base = nbase; idxH = nidxH; sv = nsv; buf ^= 1;
    }

    float den = denl;
#pragma unroll
    for (int o = 16; o > 0; o >>= 1) den += __shfl_xor_sync(0xffffffffu, den, o);

#pragma unroll
    for (int o = 8; o <= 16; o <<= 1) {
        acc.x += __shfl_xor_sync(0xffffffffu, acc.x, o);
        acc.y += __shfl_xor_sync(0xffffffffu, acc.y, o);
        acc.z += __shfl_xor_sync(0xffffffffu, acc.z, o);
        acc.w += __shfl_xor_sync(0xffffffffu, acc.w, o);
    }

    float inv = 1.f / den;
    float4 b4 = reinterpret_cast<const float4*>(b1)[q];
    float4 v4;
    v4.x = fmaxf(fmaf(acc.x, inv, b4.x), 0.f);
    v4.y = fmaxf(fmaf(acc.y, inv, b4.y), 0.f);
    v4.z = fmaxf(fmaf(acc.z, inv, b4.z), 0.f);
    v4.w = fmaxf(fmaf(acc.w, inv, b4.w), 0.f);

    if (e == 0)
        reinterpret_cast<float4*>(g_x2 + (size_t)n * HID)[q] = v4;

    // s2/d2 projections (gemm2 fused away)
    float4 ws = reinterpret_cast<const float4*>(g_w2s)[q];
    float4 wd = reinterpret_cast<const float4*>(g_w2d)[q];
    float sp = v4.x * ws.x + v4.y * ws.y + v4.z * ws.z + v4.w * ws.w;
    float dp = v4.x * wd.x + v4.y * wd.y + v4.z * wd.z + v4.w * wd.w;
    if (e != 0) { sp = 0.f; dp = 0.f; }
#pragma unroll
    for (int o = 16; o > 0; o >>= 1) {
        sp += __shfl_xor_sync(0xffffffffu, sp, o);
        dp += __shfl_xor_sync(0xffffffffu, dp, o);
    }
    if (lane == 0) { g_s2[n] = sp; g_d2[n] = dp; }
}

// ---- layer-2: aggregate x2 (dual-chunk prefetch, hybrid inner), W2 epilogue ----
struct Agg2State {
    float denl;
    float4 acc;
};

__device__ __forceinline__ void agg2_chunk(Agg2State& st, float2 (&shpw)[2][32], int& buf,
                                           int idxH, float sv, float dn, int c,
                                           int lane, int e, int lane_off) {
    float ev = sv + dn;
    ev = ev > 0.f ? ev : NEG_SLOPE * ev;
    float p = (lane < c) ? __expf(ev) : 0.f;
    st.denl += p;

    shpw[buf][lane] = make_float2(p, __int_as_float(idxH));
    __syncwarp();
    const float2* pr = &shpw[buf][e];
    if (c == 32) {
#pragma unroll
        for (int g = 0; g < 8; g++) {
            float2 qd = pr[g * 4];
            float4 hv = *reinterpret_cast<const float4*>(
                g_x2 + (__float_as_int(qd.y) + lane_off));
            st.acc.x = fmaf(qd.x, hv.x, st.acc.x);
            st.acc.y = fmaf(qd.x, hv.y, st.acc.y);
            st.acc.z = fmaf(qd.x, hv.z, st.acc.z);
            st.acc.w = fmaf(qd.x, hv.w, st.acc.w);
        }
    } else {
        int ng = (c + 3) >> 2;
        for (int g = 0; g < ng; g++) {
            float2 qd = pr[g * 4];
            float4 hv = *reinterpret_cast<const float4*>(
                g_x2 + (__float_as_int(qd.y) + lane_off));
            st.acc.x = fmaf(qd.x, hv.x, st.acc.x);
            st.acc.y = fmaf(qd.x, hv.y, st.acc.y);
            st.acc.z = fmaf(qd.x, hv.z, st.acc.z);
            st.acc.w = fmaf(qd.x, hv.w, st.acc.w);
        }
    }
    buf ^= 1;
}

__global__ __launch_bounds__(256) void k_agg2(const float* __restrict__ W2,
                                              const float* __restrict__ b2,
                                              float* __restrict__ out) {
    __shared__ float W2s[HID * NCLS];
    __shared__ float2 shp[8][2][32];
    __shared__ float4 sx[8][8];
    for (int i = threadIdx.x; i < HID * NCLS; i += blockDim.x) W2s[i] = W2[i];
    __syncthreads();

    int tid = threadIdx.x;
    int wib = tid >> 5;
    int lane = tid & 31;
    int e = lane >> 3;
    int q = lane & 7;
    int lane_off = q * 4;
    int n = (blockIdx.x * blockDim.x + tid) >> 5;
    if (n >= N_NODES) return;
    bool has2 = lane < (NCLS - 32);
    int beg = g_rowptr[n], end = g_rowptr[n + 1];
    int rem = end - beg;
    float dn = g_d2[n];
    float b2l = b2[lane];
    float b2h = has2 ? b2[lane + 32] : 0.f;

    Agg2State st; st.denl = 0.f; st.acc = make_float4(0.f, 0.f, 0.f, 0.f);
    int buf = 0;

    // dual-chunk upfront prefetch
    int iA = g_csr_idx[beg + min(lane, rem - 1)];
    bool two = rem > 32;
    int iB = 0;
    if (two) iB = g_csr_idx[beg + 32 + min(lane, rem - 33)];
    float sA = g_s2[iA >> 5];
    float sB = two ? g_s2[iB >> 5] : 0.f;

    agg2_chunk(st, shp[wib], buf, iA, sA, dn, min(32, rem), lane, e, lane_off);
    if (two)
        agg2_chunk(st, shp[wib], buf, iB, sB, dn, min(32, rem - 32), lane, e, lane_off);

    for (int base = beg + 64; base < end; base += 32) {
        int i = g_csr_idx[base + min(lane, end - base - 1)];
        float s = g_s2[i >> 5];
        agg2_chunk(st, shp[wib], buf, i, s, dn, min(32, end - base), lane, e, lane_off);
    }

    float den = st.denl;
#pragma unroll
    for (int o = 16; o > 0; o >>= 1) den += __shfl_xor_sync(0xffffffffu, den, o);

    float4 acc = st.acc;
#pragma unroll
    for (int o = 8; o <= 16; o <<= 1) {
        acc.x += __shfl_xor_sync(0xffffffffu, acc.x, o);
        acc.y += __shfl_xor_sync(0xffffffffu, acc.y, o);
        acc.z += __shfl_xor_sync(0xffffffffu, acc.z, o);
        acc.w += __shfl_xor_sync(0xffffffffu, acc.w, o);
    }
    float inv = 1.f / den;
    acc.x *= inv; acc.y *= inv; acc.z *= inv; acc.w *= inv;

    if (e == 0) sx[wib][q] = acc;
    __syncwarp();

    float o0 = b2l;
    float o1 = b2h;
#pragma unroll
    for (int k4 = 0; k4 < 8; k4++) {
        float4 xv = sx[wib][k4];
        int k = k4 * 4;
        o0 = fmaf(xv.x, W2s[(k+0) * NCLS + lane], o0);
        o0 = fmaf(xv.y, W2s[(k+1) * NCLS + lane], o0);
        o0 = fmaf(xv.z, W2s[(k+2) * NCLS + lane], o0);
        o0 = fmaf(xv.w, W2s[(k+3) * NCLS + lane], o0);
        if (has2) {
            o1 = fmaf(xv.x, W2s[(k+0) * NCLS + lane + 32], o1);
            o1 = fmaf(xv.y, W2s[(k+1) * NCLS + lane + 32], o1);
            o1 = fmaf(xv.z, W2s[(k+2) * NCLS + lane + 32], o1);
            o1 = fmaf(xv.w, W2s[(k+3) * NCLS + lane + 32], o1);
        }
    }
    float v0 = fmaxf(o0, 0.f);
    float v1 = has2 ? fmaxf(o1, 0.f) : -CUDART_INF_F;

    float m = fmaxf(v0, v1);
#pragma unroll
    for (int o = 16; o > 0; o >>= 1) m = fmaxf(m, __shfl_xor_sync(0xffffffffu, m, o));
    float se = __expf(v0 - m) + (has2 ? __expf(v1 - m) : 0.f);
#pragma unroll
    for (int o = 16; o > 0; o >>= 1) se += __shfl_xor_sync(0xffffffffu, se, o);
    float lse = m + logf(se);

    out[(size_t)n * NCLS + lane] = v0 - lse;
    if (has2) out[(size_t)n * NCLS + lane + 32] = v1 - lse;
}

// ---------------- launch ----------------
extern "C" void kernel_launch(void* const* d_in, const int* in_sizes, int n_in,
                              void* d_out, int out_size) {
    const float* x        = (const float*)d_in[0];
    const int*   edge     = (const int*)  d_in[1];
    const float* W1       = (const float*)d_in[2];
    const float* att_src1 = (const float*)d_in[3];
    const float* att_dst1 = (const float*)d_in[4];
    const float* b1       = (const float*)d_in[5];
    const float* W2       = (const float*)d_in[6];
    const float* att_src2 = (const float*)d_in[7];
    const float* att_dst2 = (const float*)d_in[8];
    const float* b2       = (const float*)d_in[9];
    float* out = (float*)d_out;

    const int* src = edge;
    const int* dst = edge + N_EDGES;

    static cudaStream_t s2 = nullptr;
    static cudaEvent_t evFork = nullptr, evJoin = nullptr;
    if (!s2) {
        cudaStreamCreateWithFlags(&s2, cudaStreamNonBlocking);
        cudaEventCreateWithFlags(&evFork, cudaEventDisableTiming);
        cudaEventCreateWithFlags(&evJoin, cudaEventDisableTiming);
    }

    // fork: gemm1 (+fused prep) runs concurrent with the CSR build
    cudaEventRecord(evFork, 0);
    cudaStreamWaitEvent(s2, evFork, 0);
    k_gemm1<<<(N_NODES + 255) / 256, 256, 0, s2>>>(x, W1, att_src1, att_dst1,
                                                   W2, att_src2, att_dst2);
    cudaEventRecord(evJoin, s2);

    // main stream: CSR build (hist big-grid; scan grid-resident; scatter big-grid)
    k_hist<<<(NQUAD + 255) / 256, 256>>>(dst);
    k_scan<<<NBLK, 256>>>();
    k_scatter<<<3125, 256>>>(src, dst);

    // join, then aggregates
    cudaStreamWaitEvent(0, evJoin, 0);
    k_agg1<<<(N_NODES * 32 + 255) / 256, 256>>>(b1);
    k_agg2<<<(N_NODES * 32 + 255) / 256, 256>>>(W2, b2, out);
}

// round 16
// speedup vs baseline: 1.1309x; 1.0687x over previous
#include <cuda_runtime.h>
#include <cuda_fp16.h>
#include <math_constants.h>

#define N_NODES 100000
#define N_EDGES 3200000
#define E_TOT   (N_EDGES + N_NODES)   // edges + self loops
#define F_IN    128
#define HID     32
#define NCLS    40
#define NEG_SLOPE 0.2f
#define NBLK    98                    // grid for scan kernel
#define NBUCKET 4
#define NQUAD (N_EDGES / 4)           // 800000 quads of edges

// ---------------- scratch (device globals; zero-initialized) ----------------
__device__ __half g_h1h[N_NODES * HID];   // x @ W1 (fp16, gather table)
__device__ __half g_x2h[N_NODES * HID];   // relu(agg1 + b1) (fp16, gather table)
__device__ float g_s1[N_NODES];           // h1 . a_src1
__device__ float g_d1[N_NODES];           // h1 . a_dst1
__device__ float g_s2[N_NODES];           // x2 . (W2 a_src2)
__device__ float g_d2[N_NODES];           // x2 . (W2 a_dst2)
__device__ float g_w2s[HID];
__device__ float g_w2d[HID];
__device__ int   g_deg[NBUCKET][N_NODES];     // bucketed degree counters (self-reset)
__device__ int   g_cursor[NBUCKET][N_NODES];  // bucketed scatter cursors
__device__ int   g_rowptr[N_NODES + 1];
__device__ int   g_csr_idx[E_TOT];            // src*HID (element offset; same for half tables)
__device__ int   g_bsum[NBLK];
__device__ int   g_ready;                     // scan arrive counter (self-reset)

// ---------------- hist: standalone big grid (1 quad/thread) ----------------
__global__ void k_hist(const int* __restrict__ dst) {
    int i = blockIdx.x * blockDim.x + threadIdx.x;
    if (i >= NQUAD) return;
    int4 d = reinterpret_cast<const int4*>(dst)[i];
    int* deg = g_deg[i & (NBUCKET - 1)];
    atomicAdd(&deg[d.x], 1);
    atomicAdd(&deg[d.y], 1);
    atomicAdd(&deg[d.z], 1);
    atomicAdd(&deg[d.w], 1);
}

// ---------------- scan: grid-resident 98 blocks, one internal grid sync ----------------
__device__ __forceinline__ void grid_sync(int threshold) {
    __syncthreads();
    if (threadIdx.x == 0) {
        __threadfence();
        atomicAdd(&g_ready, 1);
        while (((volatile int*)&g_ready)[0] < threshold) { }
    }
    __syncthreads();
}

__global__ __launch_bounds__(256) void k_scan() {
    __shared__ int sh[256];
    __shared__ int blk_off;
    int t = threadIdx.x;
    int base = blockIdx.x * 1024 + t * 4;
    int v[4];
    int dsum[4][NBUCKET];
    int s = 0;
#pragma unroll
    for (int k = 0; k < 4; k++) {
        int i = base + k;
        int d = 0;
        if (i < N_NODES) {
            d = 1;
#pragma unroll
            for (int b = 0; b < NBUCKET; b++) {
                dsum[k][b] = g_deg[b][i];
                d += dsum[k][b];
            }
        }
        v[k] = d;
        s += d;
    }
    sh[t] = s;
    __syncthreads();
    for (int off = 1; off < 256; off <<= 1) {
        int u = (t >= off) ? sh[t - off] : 0;
        __syncthreads();
        sh[t] += u;
        __syncthreads();
    }
    int thr_excl = sh[t] - s;
    if (t == 0) g_bsum[blockIdx.x] = sh[255];
    grid_sync(NBLK);
    if (t == 0) {
        int off = 0;
        for (int b = 0; b < (int)blockIdx.x; b++) off += g_bsum[b];
        blk_off = off;
    }
    __syncthreads();

    int run = blk_off + thr_excl;
#pragma unroll
    for (int k = 0; k < 4; k++) {
        int i = base + k;
        if (i < N_NODES) {
            g_rowptr[i] = run;
            g_csr_idx[run] = i * HID;        // self loop at head (pre-scaled)
            int c = run + 1;
#pragma unroll
            for (int b = 0; b < NBUCKET; b++) {
                g_cursor[b][i] = c;
                c += dsum[k][b];
            }
        }
        run += v[k];
    }
    if (blockIdx.x == NBLK - 1 && t == 255) g_rowptr[N_NODES] = E_TOT;
}

// ---------------- scatter (big grid, idx only) + state reset ----------------
__global__ void k_scatter(const int* __restrict__ src, const int* __restrict__ dst) {
    int gtid = blockIdx.x * blockDim.x + threadIdx.x;
    int gsz = gridDim.x * blockDim.x;

    for (int i = gtid; i < NQUAD; i += gsz) {
        int4 s4 = reinterpret_cast<const int4*>(src)[i];
        int4 d4 = reinterpret_cast<const int4*>(dst)[i];
        int* cur = g_cursor[i & (NBUCKET - 1)];
        int p0 = atomicAdd(&cur[d4.x], 1);
        int p1 = atomicAdd(&cur[d4.y], 1);
        int p2 = atomicAdd(&cur[d4.z], 1);
        int p3 = atomicAdd(&cur[d4.w], 1);
        g_csr_idx[p0] = s4.x * HID;
        g_csr_idx[p1] = s4.y * HID;
        g_csr_idx[p2] = s4.z * HID;
        g_csr_idx[p3] = s4.w * HID;
    }

    // reset state for next graph replay
    for (int i = gtid; i < N_NODES; i += gsz) {
#pragma unroll
        for (int b = 0; b < NBUCKET; b++) g_deg[b][i] = 0;
    }
    if (gtid == 0) g_ready = 0;
}

// ---------------- GEMM1 (+fused prep): h1h = fp16(x @ W1), s1/d1; block 0: w2s/w2d ----
__global__ __launch_bounds__(256) void k_gemm1(const float* __restrict__ x,
                                               const float* __restrict__ W1,
                                               const float* __restrict__ a_src,
                                               const float* __restrict__ a_dst,
                                               const float* __restrict__ W2,
                                               const float* __restrict__ a_src2,
                                               const float* __restrict__ a_dst2) {
    __shared__ float Ws[F_IN * HID];
    __shared__ float asv[HID], adv[HID];
    for (int i = threadIdx.x; i < F_IN * HID; i += blockDim.x) Ws[i] = W1[i];
    if (threadIdx.x < HID) { asv[threadIdx.x] = a_src[threadIdx.x]; adv[threadIdx.x] = a_dst[threadIdx.x]; }

    if (blockIdx.x == 0 && threadIdx.x >= 224) {
        int k = threadIdx.x - 224;   // 0..31
        float s = 0.f, d = 0.f;
        const float* row = W2 + k * NCLS;
#pragma unroll
        for (int c = 0; c < NCLS; c++) {
            s = fmaf(row[c], a_src2[c], s);
            d = fmaf(row[c], a_dst2[c], d);
        }
        g_w2s[k] = s;
        g_w2d[k] = d;
    }
    __syncthreads();

    int n = blockIdx.x * blockDim.x + threadIdx.x;
    if (n >= N_NODES) return;

    float acc[HID];
#pragma unroll
    for (int c = 0; c < HID; c++) acc[c] = 0.f;

    const float4* xr = reinterpret_cast<const float4*>(x + (size_t)n * F_IN);
    const float4* Ws4 = reinterpret_cast<const float4*>(Ws);
#pragma unroll 4
    for (int k4 = 0; k4 < F_IN / 4; k4++) {
        float4 xv = xr[k4];
        int r = (k4 * 4) * (HID / 4);
#pragma unroll
        for (int c4 = 0; c4 < HID / 4; c4++) {
            float4 w0 = Ws4[r + c4];
            float4 w1 = Ws4[r + (HID / 4) + c4];
            float4 w2 = Ws4[r + 2 * (HID / 4) + c4];
            float4 w3 = Ws4[r + 3 * (HID / 4) + c4];
            int c = c4 * 4;
            acc[c+0] = fmaf(xv.x, w0.x, fmaf(xv.y, w1.x, fmaf(xv.z, w2.x, fmaf(xv.w, w3.x, acc[c+0]))));
            acc[c+1] = fmaf(xv.x, w0.y, fmaf(xv.y, w1.y, fmaf(xv.z, w2.y, fmaf(xv.w, w3.y, acc[c+1]))));
            acc[c+2] = fmaf(xv.x, w0.z, fmaf(xv.y, w1.z, fmaf(xv.z, w2.z, fmaf(xv.w, w3.z, acc[c+2]))));
            acc[c+3] = fmaf(xv.x, w0.w, fmaf(xv.y, w1.w, fmaf(xv.z, w2.w, fmaf(xv.w, w3.w, acc[c+3]))));
        }
    }
    float sv = 0.f, dv = 0.f;
    __half2 hb[HID / 2];
#pragma unroll
    for (int c = 0; c < HID; c += 2) {
        hb[c / 2] = __floats2half2_rn(acc[c], acc[c + 1]);
        sv = fmaf(acc[c], asv[c], sv);
        sv = fmaf(acc[c+1], asv[c+1], sv);
        dv = fmaf(acc[c], adv[c], dv);
        dv = fmaf(acc[c+1], adv[c+1], dv);
    }
    uint4* dstv = reinterpret_cast<uint4*>(&g_h1h[(size_t)n * HID]);
    const uint4* sv4 = reinterpret_cast<const uint4*>(hb);
    dstv[0] = sv4[0]; dstv[1] = sv4[1]; dstv[2] = sv4[2]; dstv[3] = sv4[3];
    g_s1[n] = sv;
    g_d1[n] = dv;
}

// fp16 row fragment FMA: 8 halves, one weight
__device__ __forceinline__ void h8_fma(float acc[8], float p, uint4 hv) {
    const __half2* h2 = reinterpret_cast<const __half2*>(&hv);
    float2 f0 = __half22float2(h2[0]);
    float2 f1 = __half22float2(h2[1]);
    float2 f2 = __half22float2(h2[2]);
    float2 f3 = __half22float2(h2[3]);
    acc[0] = fmaf(p, f0.x, acc[0]); acc[1] = fmaf(p, f0.y, acc[1]);
    acc[2] = fmaf(p, f1.x, acc[2]); acc[3] = fmaf(p, f1.y, acc[3]);
    acc[4] = fmaf(p, f2.x, acc[4]); acc[5] = fmaf(p, f2.y, acc[5]);
    acc[6] = fmaf(p, f3.x, acc[6]); acc[7] = fmaf(p, f3.y, acc[7]);
}

// ---- layer-1 aggregate: 8-edge-slot fp16 gather (LDG.128 = 8 halves/lane) ----
__global__ __launch_bounds__(256) void k_agg1(const float* __restrict__ b1) {
    __shared__ float2 shp[8][2][32];
    int tid = threadIdx.x;
    int wib = tid >> 5;
    int lane = tid & 31;
    int e = lane >> 2;        // edge slot 0..7
    int q = lane & 3;         // row quarter 0..3 (8 halves each)
    int n = (blockIdx.x * blockDim.x + tid) >> 5;
    if (n >= N_NODES) return;
    int beg = g_rowptr[n], end = g_rowptr[n + 1];
    float dn = g_d1[n];
    const __half* hbase = g_h1h + q * 8;

    float denl = 0.f;
    float acc[8];
#pragma unroll
    for (int j = 0; j < 8; j++) acc[j] = 0.f;
    int buf = 0;

    int base = beg;
    int idxH = g_csr_idx[base + min(lane, end - base - 1)];
    float sv  = g_s1[idxH >> 5];

    while (base < end) {
        int c = min(32, end - base);
        int nbase = base + 32;
        int nidxH = 0; float nsv = 0.f;
        if (nbase < end) {   // prefetch next chunk scalars
            nidxH = g_csr_idx[nbase + min(lane, end - nbase - 1)];
            nsv   = g_s1[nidxH >> 5];
        }

        float ev = sv + dn;
        ev = ev > 0.f ? ev : NEG_SLOPE * ev;
        float p = (lane < c) ? __expf(ev) : 0.f;
        denl += p;

        shp[wib][buf][lane] = make_float2(p, __int_as_float(idxH));
        __syncwarp();
        const float2* pr = &shp[wib][buf][e];
        if (c == 32) {
#pragma unroll
            for (int g = 0; g < 4; g++) {
                float2 qd = pr[g * 8];
                uint4 hv = *reinterpret_cast<const uint4*>(hbase + __float_as_int(qd.y));
                h8_fma(acc, qd.x, hv);
            }
        } else {
            int ng = (c + 7) >> 3;
            for (int g = 0; g < ng; g++) {
                float2 qd = pr[g * 8];
                uint4 hv = *reinterpret_cast<const uint4*>(hbase + __float_as_int(qd.y));
                h8_fma(acc, qd.x, hv);
            }
        }
        base = nbase; idxH = nidxH; sv = nsv; buf ^= 1;
    }

    float den = denl;
#pragma unroll
    for (int o = 16; o > 0; o >>= 1) den += __shfl_xor_sync(0xffffffffu, den, o);

    // reduce acc across edge slots (lane bits 2,3,4)
#pragma unroll
    for (int o = 4; o <= 16; o <<= 1) {
#pragma unroll
        for (int j = 0; j < 8; j++)
            acc[j] += __shfl_xor_sync(0xffffffffu, acc[j], o);
    }

    float inv = 1.f / den;
    float v[8];
#pragma unroll
    for (int j = 0; j < 8; j++)
        v[j] = fmaxf(fmaf(acc[j], inv, b1[q * 8 + j]), 0.f);

    if (e == 0) {
        __half2 ob[4];
#pragma unroll
        for (int j = 0; j < 4; j++) ob[j] = __floats2half2_rn(v[2 * j], v[2 * j + 1]);
        *reinterpret_cast<uint4*>(&g_x2h[(size_t)n * HID + q * 8]) =
            *reinterpret_cast<const uint4*>(ob);
    }

    // s2/d2 projections (gemm2 fused away)
    float sp = 0.f, dp = 0.f;
#pragma unroll
    for (int j = 0; j < 8; j++) {
        sp = fmaf(v[j], g_w2s[q * 8 + j], sp);
        dp = fmaf(v[j], g_w2d[q * 8 + j], dp);
    }
    if (e != 0) { sp = 0.f; dp = 0.f; }
    sp += __shfl_xor_sync(0xffffffffu, sp, 1);
    dp += __shfl_xor_sync(0xffffffffu, dp, 1);
    sp += __shfl_xor_sync(0xffffffffu, sp, 2);
    dp += __shfl_xor_sync(0xffffffffu, dp, 2);
    if (lane == 0) { g_s2[n] = sp; g_d2[n] = dp; }
}

// ---- layer-2: fp16 x2 gather, W2 epilogue + bias + relu + log_softmax ----
__global__ __launch_bounds__(256) void k_agg2(const float* __restrict__ W2,
                                              const float* __restrict__ b2,
                                              float* __restrict__ out) {
    __shared__ float W2s[HID * NCLS];
    __shared__ float2 shp[8][2][32];
    __shared__ float4 sx4[8][8];
    for (int i = threadIdx.x; i < HID * NCLS; i += blockDim.x) W2s[i] = W2[i];
    __syncthreads();

    int tid = threadIdx.x;
    int wib = tid >> 5;
    int lane = tid & 31;
    int e = lane >> 2;
    int q = lane & 3;
    int n = (blockIdx.x * blockDim.x + tid) >> 5;
    if (n >= N_NODES) return;
    bool has2 = lane < (NCLS - 32);
    int beg = g_rowptr[n], end = g_rowptr[n + 1];
    float dn = g_d2[n];
    float b2l = b2[lane];
    float b2h = has2 ? b2[lane + 32] : 0.f;
    const __half* hbase = g_x2h + q * 8;

    float denl = 0.f;
    float acc[8];
#pragma unroll
    for (int j = 0; j < 8; j++) acc[j] = 0.f;
    int buf = 0;

    int base = beg;
    int idxH = g_csr_idx[base + min(lane, end - base - 1)];
    float sv  = g_s2[idxH >> 5];

    while (base < end) {
        int c = min(32, end - base);
        int nbase = base + 32;
        int nidxH = 0; float nsv = 0.f;
        if (nbase < end) {
            nidxH = g_csr_idx[nbase + min(lane, end - nbase - 1)];
            nsv   = g_s2[nidxH >> 5];
        }

        float ev = sv + dn;
        ev = ev > 0.f ? ev : NEG_SLOPE * ev;
        float p = (lane < c) ? __expf(ev) : 0.f;
        denl += p;

        shp[wib][buf][lane] = make_float2(p, __int_as_float(idxH));
        __syncwarp();
        const float2* pr = &shp[wib][buf][e];
        if (c == 32) {
#pragma unroll
            for (int g = 0; g < 4; g++) {
                float2 qd = pr[g * 8];
                uint4 hv = *reinterpret_cast<const uint4*>(hbase + __float_as_int(qd.y));
                h8_fma(acc, qd.x, hv);
            }
        } else {
            int ng = (c + 7) >> 3;
            for (int g = 0; g < ng; g++) {
                float2 qd = pr[g * 8];
                uint4 hv = *reinterpret_cast<const uint4*>(hbase + __float_as_int(qd.y));
                h8_fma(acc, qd.x, hv);
            }
        }
        base = nbase; idxH = nidxH; sv = nsv; buf ^= 1;
    }

    float den = denl;
#pragma unroll
    for (int o = 16; o > 0; o >>= 1) den += __shfl_xor_sync(0xffffffffu, den, o);

#pragma unroll
    for (int o = 4; o <= 16; o <<= 1) {
#pragma unroll
        for (int j = 0; j < 8; j++)
            acc[j] += __shfl_xor_sync(0xffffffffu, acc[j], o);
    }
    float inv = 1.f / den;

    if (e == 0) {
        float* sxf = reinterpret_cast<float*>(sx4[wib]);
#pragma unroll
        for (int j = 0; j < 8; j++) sxf[q * 8 + j] = acc[j] * inv;
    }
    __syncwarp();

    // epilogue GEMM: h_out[c] = sum_k aggx_k * W2[k][c] + b2[c]
    float o0 = b2l;
    float o1 = b2h;
#pragma unroll
    for (int k4 = 0; k4 < 8; k4++) {
        float4 xv = sx4[wib][k4];
        int k = k4 * 4;
        o0 = fmaf(xv.x, W2s[(k+0) * NCLS + lane], o0);
        o0 = fmaf(xv.y, W2s[(k+1) * NCLS + lane], o0);
        o0 = fmaf(xv.z, W2s[(k+2) * NCLS + lane], o0);
        o0 = fmaf(xv.w, W2s[(k+3) * NCLS + lane], o0);
        if (has2) {
            o1 = fmaf(xv.x, W2s[(k+0) * NCLS + lane + 32], o1);
            o1 = fmaf(xv.y, W2s[(k+1) * NCLS + lane + 32], o1);
            o1 = fmaf(xv.z, W2s[(k+2) * NCLS + lane + 32], o1);
            o1 = fmaf(xv.w, W2s[(k+3) * NCLS + lane + 32], o1);
        }
    }
    float v0 = fmaxf(o0, 0.f);
    float v1 = has2 ? fmaxf(o1, 0.f) : -CUDART_INF_F;

    float m = fmaxf(v0, v1);
#pragma unroll
    for (int o = 16; o > 0; o >>= 1) m = fmaxf(m, __shfl_xor_sync(0xffffffffu, m, o));
    float se = __expf(v0 - m) + (has2 ? __expf(v1 - m) : 0.f);
#pragma unroll
    for (int o = 16; o > 0; o >>= 1) se += __shfl_xor_sync(0xffffffffu, se, o);
    float lse = m + logf(se);

    out[(size_t)n * NCLS + lane] = v0 - lse;
    if (has2) out[(size_t)n * NCLS + lane + 32] = v1 - lse;
}

// ---------------- launch ----------------
extern "C" void kernel_launch(void* const* d_in, const int* in_sizes, int n_in,
                              void* d_out, int out_size) {
    const float* x        = (const float*)d_in[0];
    const int*   edge     = (const int*)  d_in[1];
    const float* W1       = (const float*)d_in[2];
    const float* att_src1 = (const float*)d_in[3];
    const float* att_dst1 = (const float*)d_in[4];
    const float* b1       = (const float*)d_in[5];
    const float* W2       = (const float*)d_in[6];
    const float* att_src2 = (const float*)d_in[7];
    const float* att_dst2 = (const float*)d_in[8];
    const float* b2       = (const float*)d_in[9];
    float* out = (float*)d_out;

    const int* src = edge;
    const int* dst = edge + N_EDGES;

    static cudaStream_t s2 = nullptr;
    static cudaEvent_t evFork = nullptr, evJoin = nullptr;
    if (!s2) {
        cudaStreamCreateWithFlags(&s2, cudaStreamNonBlocking);
        cudaEventCreateWithFlags(&evFork, cudaEventDisableTiming);
        cudaEventCreateWithFlags(&evJoin, cudaEventDisableTiming);
    }

    // fork: gemm1 (+fused prep) runs concurrent with the CSR build
    cudaEventRecord(evFork, 0);
    cudaStreamWaitEvent(s2, evFork, 0);
    k_gemm1<<<(N_NODES + 255) / 256, 256, 0, s2>>>(x, W1, att_src1, att_dst1,
                                                   W2, att_src2, att_dst2);
    cudaEventRecord(evJoin, s2);

    // main stream: CSR build (hist big-grid; scan grid-resident; scatter big-grid)
    k_hist<<<(NQUAD + 255) / 256, 256>>>(dst);
    k_scan<<<NBLK, 256>>>();
    k_scatter<<<3125, 256>>>(src, dst);

    // join, then aggregates
    cudaStreamWaitEvent(0, evJoin, 0);
    k_agg1<<<(N_NODES * 32 + 255) / 256, 256>>>(b1);
    k_agg2<<<(N_NODES * 32 + 255) / 256, 256>>>(W2, b2, out);
}